// round 15
// baseline (speedup 1.0000x reference)
#include <cuda_runtime.h>
#include <cuda_fp16.h>
#include <cstdint>

// ============================================================================
// TT-linear = densify W -> 2-term split-fp16 tcgen05 GEMM (cg2, 256x256).
// R15: kill the per-kstep sync tax. All mbarrier waits demoted from
// acquire.cluster (emits L1-invalidating CCTL.IVALL per waiter) to
// relaxed.cta / acquire.cta, and waiter sets shrunk to 1 lane per warp.
//   y ~= (A_hi + A_lo) . B_hi  (fp16 ins, fp32 accum), rel_err ~2e-4.
// ============================================================================

#if defined(__CUDA_ARCH_FEAT_SM103_ALL) || defined(__CUDA_ARCH_FEAT_SM100_ALL) || defined(__CUDA_ARCH_FEAT_SM101_ALL)
#define HAS_TCGEN05 1
#endif

typedef unsigned long long u64;

__device__ __half g_Ahi[4096u * 4096u];
__device__ __half g_Alo[4096u * 4096u];
__device__ __half g_Bhi[4096u * 4096u];   // K-major: [n][m]

// -------- arch-neutral helpers --------
__device__ __forceinline__ uint32_t smem_u32(const void* p) {
    uint32_t a;
    asm("{ .reg .u64 t; cvta.to.shared.u64 t, %1; cvt.u32.u64 %0, t; }"
        : "=r"(a) : "l"(p));
    return a;
}
__device__ __forceinline__ uint32_t cta_rank() {
    uint32_t r; asm("mov.u32 %0, %%cluster_ctarank;" : "=r"(r)); return r;
}
__device__ __forceinline__ void cpasync16(uint32_t dst, const void* src) {
    asm volatile("cp.async.cg.shared.global [%0], [%1], 16;"
                 :: "r"(dst), "l"(src) : "memory");
}
__device__ __forceinline__ void cp_commit() {
    asm volatile("cp.async.commit_group;" ::: "memory");
}
__device__ __forceinline__ void cp_wait3() {
    asm volatile("cp.async.wait_group 3;" ::: "memory");
}

#define MBARRIER_INIT(addr, cnt) \
    asm volatile("mbarrier.init.shared.b64 [%0], %1;" \
                 :: "r"((uint32_t)(addr)), "r"((uint32_t)(cnt)) : "memory")

#define MBAR_ARRIVE_CLU(addr, rk) \
    asm volatile("{\n\t.reg .b32 ra;\n\t" \
                 "mapa.shared::cluster.u32 ra, %0, %1;\n\t" \
                 "mbarrier.arrive.shared::cluster.b64 _, [ra];\n\t}" \
                 :: "r"((uint32_t)(addr)), "r"((uint32_t)(rk)) : "memory")

// acquire at CTA scope (consumer needs data visibility in generic/async proxy)
#define MBAR_WAIT_ACQ_CTA(addr, par) do {                                   \
    uint32_t _m = (uint32_t)(addr);                                         \
    uint32_t _p = (uint32_t)(par);                                          \
    asm volatile(                                                           \
        "{\n\t.reg .pred P;\n\t"                                            \
        "WL_%=:\n\t"                                                        \
        "mbarrier.try_wait.parity.acquire.cta.shared::cta.b64 P, [%0], %1, 0x989680;\n\t" \
        "@P bra.uni WD_%=;\n\t"                                             \
        "bra.uni WL_%=;\n\t"                                                \
        "WD_%=:\n\t}"                                                       \
        :: "r"(_m), "r"(_p) : "memory");                                    \
} while (0)

// relaxed (completion-causality only; post-wait accesses are async-proxy)
#define MBAR_WAIT_RLX_CTA(addr, par) do {                                   \
    uint32_t _m = (uint32_t)(addr);                                         \
    uint32_t _p = (uint32_t)(par);                                          \
    asm volatile(                                                           \
        "{\n\t.reg .pred P;\n\t"                                            \
        "WL_%=:\n\t"                                                        \
        "mbarrier.try_wait.parity.relaxed.cta.shared::cta.b64 P, [%0], %1, 0x989680;\n\t" \
        "@P bra.uni WD_%=;\n\t"                                             \
        "bra.uni WL_%=;\n\t"                                                \
        "WD_%=:\n\t}"                                                       \
        :: "r"(_m), "r"(_p) : "memory");                                    \
} while (0)

#define FENCE_PROXY_ASYNC() asm volatile("fence.proxy.async;" ::: "memory")

#ifdef HAS_TCGEN05
#define TCGEN05_ALLOC_CG2(sa, n) \
    asm volatile("tcgen05.alloc.cta_group::2.sync.aligned.shared::cta.b32 [%0], %1;" \
                 :: "r"((uint32_t)(sa)), "r"((uint32_t)(n)) : "memory")
#define TCGEN05_DEALLOC_CG2(tm, n) \
    asm volatile("tcgen05.dealloc.cta_group::2.sync.aligned.b32 %0, %1;" \
                 :: "r"(tm), "r"((uint32_t)(n)))
#define TCGEN05_RELINQ_CG2() \
    asm volatile("tcgen05.relinquish_alloc_permit.cta_group::2.sync.aligned;")
#define TCGEN05_COMMIT_MC_CG2(mbar, mask) \
    asm volatile("tcgen05.commit.cta_group::2.mbarrier::arrive::one.shared::cluster.multicast::cluster.b64 [%0], %1;" \
                 :: "r"((uint32_t)(mbar)), "h"((uint16_t)(mask)) : "memory")
#define TCGEN05_FENCE_AFTER() \
    asm volatile("tcgen05.fence::after_thread_sync;" ::: "memory")
#define TCGEN05_FENCE_BEFORE() \
    asm volatile("tcgen05.fence::before_thread_sync;" ::: "memory")
#define TCGEN05_WAIT_LD() \
    asm volatile("tcgen05.wait::ld.sync.aligned;" ::: "memory")

#define TCGEN05_LD_X32(r, ta) \
    asm volatile( \
        "tcgen05.ld.sync.aligned.32x32b.x32.b32 " \
        "{%0, %1, %2, %3, %4, %5, %6, %7, " \
        " %8, %9, %10, %11, %12, %13, %14, %15, " \
        " %16, %17, %18, %19, %20, %21, %22, %23, " \
        " %24, %25, %26, %27, %28, %29, %30, %31}, [%32];" \
        : "=r"((r)[0]),  "=r"((r)[1]),  "=r"((r)[2]),  "=r"((r)[3]), \
          "=r"((r)[4]),  "=r"((r)[5]),  "=r"((r)[6]),  "=r"((r)[7]), \
          "=r"((r)[8]),  "=r"((r)[9]),  "=r"((r)[10]), "=r"((r)[11]), \
          "=r"((r)[12]), "=r"((r)[13]), "=r"((r)[14]), "=r"((r)[15]), \
          "=r"((r)[16]), "=r"((r)[17]), "=r"((r)[18]), "=r"((r)[19]), \
          "=r"((r)[20]), "=r"((r)[21]), "=r"((r)[22]), "=r"((r)[23]), \
          "=r"((r)[24]), "=r"((r)[25]), "=r"((r)[26]), "=r"((r)[27]), \
          "=r"((r)[28]), "=r"((r)[29]), "=r"((r)[30]), "=r"((r)[31]) \
        : "r"(ta))

__device__ __forceinline__ void mma_f16_ss_cg2(
    uint32_t d_tmem, u64 a_desc, u64 b_desc, uint32_t idesc, bool en)
{
    uint32_t e = en ? 1u : 0u;
    asm volatile(
        "{\n\t.reg .pred p;\n\t"
        "setp.ne.u32 p, %6, 0;\n\t"
        "tcgen05.mma.cta_group::2.kind::f16 [%0], %1, %2, %3, "
        "{%4, %4, %4, %4, %4, %4, %4, %4}, p;\n\t}"
        :: "r"(d_tmem), "l"(a_desc), "l"(b_desc), "r"(idesc),
           "r"(0u), "r"(0u), "r"(e)
        : "memory");
}

static constexpr u64 SMEM_DESC_SW128 =
    (u64(2) << 61) | (u64(1) << 46) | (u64(64) << 32) | (u64(1) << 16);
__device__ __forceinline__ u64 mk_desc(uint32_t a) {
    return SMEM_DESC_SW128 | ((u64)(a >> 4) & 0x3FFF);
}
#endif  // HAS_TCGEN05

// ============================================================================
// Kernel 1: split x into fp16 hi/lo
// ============================================================================
__global__ __launch_bounds__(256) void k_split_x(const float* __restrict__ xg)
{
    const float4* x4 = (const float4*)xg;
    uint32_t* ahi = (uint32_t*)g_Ahi;
    uint32_t* alo = (uint32_t*)g_Alo;
    int stride = gridDim.x * blockDim.x;
    for (int q = blockIdx.x * blockDim.x + threadIdx.x; q < 4194304; q += stride) {
        float4 v = x4[q];
        __half h0 = __float2half_rn(v.x);
        __half h1 = __float2half_rn(v.y);
        __half h2 = __float2half_rn(v.z);
        __half h3 = __float2half_rn(v.w);
        __half l0 = __float2half_rn(v.x - __half2float(h0));
        __half l1 = __float2half_rn(v.y - __half2float(h1));
        __half l2 = __float2half_rn(v.z - __half2float(h2));
        __half l3 = __float2half_rn(v.w - __half2float(h3));
        __half2 hh0 = {h0, h1}, hh1 = {h2, h3};
        __half2 ll0 = {l0, l1}, ll1 = {l2, l3};
        ahi[2 * q]     = *(uint32_t*)&hh0;
        ahi[2 * q + 1] = *(uint32_t*)&hh1;
        alo[2 * q]     = *(uint32_t*)&ll0;
        alo[2 * q + 1] = *(uint32_t*)&ll1;
    }
}

// ============================================================================
// Kernel 2: densify W^T (K-major [n][m]) into fp16
// ============================================================================
__global__ __launch_bounds__(256) void k_densify(const float* __restrict__ c0g,
                                                 const float* __restrict__ c1g,
                                                 const float* __restrict__ c2g)
{
    __shared__ float sE[2048];
    __shared__ float sc2[2048];
    const int tid = threadIdx.x;
    const int m1 = blockIdx.x >> 4;
    const int m2 = blockIdx.x & 15;
    const int n1 = tid >> 4, n2 = tid & 15;

    float c0r[8];
#pragma unroll
    for (int r1 = 0; r1 < 8; ++r1) c0r[r1] = c0g[m1 * 128 + n1 * 8 + r1];
#pragma unroll
    for (int r2 = 0; r2 < 8; ++r2) {
        float acc = 0.0f;
#pragma unroll
        for (int r1 = 0; r1 < 8; ++r1)
            acc += c0r[r1] * c1g[(r1 * 16 + m2) * 128 + n2 * 8 + r2];
        sE[tid * 8 + r2] = acc;
    }
    for (int i = tid; i < 2048; i += 256) sc2[i] = c2g[i];
    __syncthreads();

    float Er[8];
#pragma unroll
    for (int r2 = 0; r2 < 8; ++r2) Er[r2] = sE[tid * 8 + r2];

#pragma unroll 1
    for (int n3 = 0; n3 < 16; ++n3) {
        __half hv[16];
#pragma unroll
        for (int m3 = 0; m3 < 16; ++m3) {
            float w = 0.0f;
#pragma unroll
            for (int r2 = 0; r2 < 8; ++r2)
                w += Er[r2] * sc2[r2 * 256 + m3 * 16 + n3];
            hv[m3] = __float2half_rn(w);
        }
        const int n = n1 * 256 + n2 * 16 + n3;
        const size_t boff = (size_t)n * 4096 + m1 * 256 + m2 * 16;
        *(uint4*)(g_Bhi + boff)     = ((uint4*)hv)[0];
        *(uint4*)(g_Bhi + boff + 8) = ((uint4*)hv)[1];
    }
}

// ============================================================================
// Kernel 3: persistent cg2 tcgen05 GEMM.
// 76 clusters x (3..4) 256x256 tiles. KB=64, 4 stages (48KB each).
// Warps: 0 MMA (leader) | 1-6 loaders (192 thr) | 8-11 epilogue.
// ============================================================================
static constexpr int KPT = 64;                 // ksteps per tile (K=4096, KB=64)
static constexpr uint32_t GIDESC =
    (1u << 4) | (32u << 17) | (16u << 24);     // F32 accum, F16 a/b, N=256, M=256

static constexpr int OFF_TMEM  = 0;
static constexpr int OFF_READY = 16;           // 4 x 8B
static constexpr int OFF_DONE  = 48;           // 4 x 8B
static constexpr int OFF_TDONE = 80;           // 8B
static constexpr int OFF_EPI   = 96;           // 2 x 8B
static constexpr int OFF_TILES = 1024;
static constexpr int STAGE_BYTES = 3 * 16384;  // Ahi, Alo, B (16KB each)
static constexpr int GEMM_SMEM = 1024 + 4 * STAGE_BYTES;   // 197632 B

__global__ __launch_bounds__(384, 1) __cluster_dims__(2, 1, 1)
void k_gemm(const float* __restrict__ xg, const float* __restrict__ biasg,
            float* __restrict__ outg)
{
#ifdef HAS_TCGEN05
    extern __shared__ char smem[];
    const uint32_t sb = smem_u32(smem);
    const int tid = threadIdx.x;
    const int wid = tid >> 5;
    const int lane = tid & 31;
    const uint32_t rank = cta_rank();
    const int cid = blockIdx.x >> 1;               // cluster id, 0..75

    const int nt = (cid < 28) ? 4 : 3;             // tiles this cluster (256=3*76+28)
    const int GT = nt * KPT;                       // total flat ksteps

    if (tid == 0) {
#pragma unroll
        for (int s = 0; s < 4; ++s) {
            MBARRIER_INIT(sb + OFF_READY + s * 8, 2);
            MBARRIER_INIT(sb + OFF_DONE + s * 8, 1);
        }
        MBARRIER_INIT(sb + OFF_TDONE, 1);
        MBARRIER_INIT(sb + OFF_EPI, 2);
        MBARRIER_INIT(sb + OFF_EPI + 8, 2);
    }
    if (wid == 0) TCGEN05_ALLOC_CG2(sb + OFF_TMEM, 512);
    __syncthreads();
    uint32_t tmem;
    asm volatile("ld.shared.b32 %0, [%1];" : "=r"(tmem) : "r"(sb + OFF_TMEM));

    asm volatile("barrier.cluster.arrive.aligned;" ::: "memory");
    asm volatile("barrier.cluster.wait.aligned;" ::: "memory");

    // ---------------- loaders: warps 1-6 (lt = 0..191) ----------------
    if (wid >= 1 && wid <= 6) {
        const int lt = tid - 32;
        const int tt = lt >> 6;                  // tensor 0 Ahi, 1 Alo, 2 Bhi
        const int r0 = (lt & 63) * 2;            // rows r0, r0+1 of the tile
        const __half* gbase = (tt == 0) ? g_Ahi : (tt == 1) ? g_Alo : g_Bhi;
        const uint32_t dst0 = sb + OFF_TILES + tt * 16384 + r0 * 128;
        const int p0 = (r0 & 7) << 4;            // swizzle perm of row r0
        const int p1 = ((r0 + 1) & 7) << 4;

        const __half* sp0 = nullptr;
        int cur_tile = -1;

        auto set_tile = [&](int t) {
            const int pr = cid + t * 76;
            const int rowbase = (tt < 2) ? ((pr >> 4) * 256 + (int)rank * 128)
                                         : ((pr & 15) * 256 + (int)rank * 128);
            sp0 = gbase + (size_t)(rowbase + r0) * 4096;
            cur_tile = t;
        };
        auto issue = [&](int gks) {
            const int t = gks >> 6;
            if (t != cur_tile) set_tile(t);
            const uint32_t stg = dst0 + (gks & 3) * STAGE_BYTES;
            const __half* s0 = sp0 + (gks & 63) * 64;
            const __half* s1 = s0 + 4096;
#pragma unroll
            for (int w8 = 0; w8 < 8; ++w8)
                cpasync16(stg + ((w8 << 4) ^ p0), s0 + w8 * 8);
#pragma unroll
            for (int w8 = 0; w8 < 8; ++w8)
                cpasync16(stg + 128 + ((w8 << 4) ^ p1), s1 + w8 * 8);
            cp_commit();
        };

        issue(0); issue(1); issue(2); issue(3);

        for (int gks = 4; gks < GT + 4; ++gks) {
            // 1) publish ready(gks-4) as soon as its data lands
            cp_wait3();                            // group gks-4 landed
            FENCE_PROXY_ASYNC();
            asm volatile("bar.sync 1, 192;" ::: "memory");
            if (lt == 0)
                MBAR_ARRIVE_CLU(sb + OFF_READY + ((gks - 4) & 3) * 8, 0);
            // 2) refill stage gks&3 after MMA(gks-4) released it.
            //    One waiter lane per warp, relaxed CTA scope (no L1 flush).
            if (gks < GT) {
                if ((lt & 31) == 0)
                    MBAR_WAIT_RLX_CTA(sb + OFF_DONE + (gks & 3) * 8,
                                      (uint32_t)(((gks - 4) >> 2) & 1));
                __syncwarp();
                issue(gks);
            } else {
                cp_commit();                       // empty group keeps counts aligned
            }
        }
    }
    // ---------------- MMA: warp 0 of leader CTA, lane 0 only ----------------
    else if (wid == 0 && rank == 0) {
        if (lane == 0) {
            for (int t = 0; t < nt; ++t) {
                const int b = t & 1;
                const uint32_t Dt = tmem + b * 256;
                if (t >= 2)
                    MBAR_WAIT_RLX_CTA(sb + OFF_EPI + b * 8,
                                      (uint32_t)(((t >> 1) - 1) & 1));
                for (int k = 0; k < KPT; ++k) {
                    const int gks = t * KPT + k;
                    const int s = gks & 3;
                    MBAR_WAIT_ACQ_CTA(sb + OFF_READY + s * 8,
                                      (uint32_t)((gks >> 2) & 1));
                    const uint32_t stg = sb + OFF_TILES + s * STAGE_BYTES;
                    const u64 dA = mk_desc(stg);
                    const u64 dL = mk_desc(stg + 16384);
                    const u64 dB = mk_desc(stg + 32768);
#pragma unroll
                    for (int j = 0; j < 4; ++j)
                        mma_f16_ss_cg2(Dt, dA + j * 2, dB + j * 2, GIDESC,
                                       !(k == 0 && j == 0));
#pragma unroll
                    for (int j = 0; j < 4; ++j)
                        mma_f16_ss_cg2(Dt, dL + j * 2, dB + j * 2, GIDESC, true);
                    TCGEN05_COMMIT_MC_CG2(sb + OFF_DONE + s * 8, 0x3);
                    if (k == KPT - 1)
                        TCGEN05_COMMIT_MC_CG2(sb + OFF_TDONE, 0x3);
                }
            }
        }
    }
    // ---------------- epilogue: warps 8-11 (both CTAs) ----------------
    else if (wid >= 8) {
        const int sp = wid - 8;                  // subpartition (hw warp%4)
        for (int t = 0; t < nt; ++t) {
            MBAR_WAIT_ACQ_CTA(sb + OFF_TDONE, (uint32_t)(t & 1));
            TCGEN05_FENCE_AFTER();
            const int b = t & 1;
            const uint32_t Dt = tmem + b * 256;
            const int pr = cid + t * 76;
            const int mtile = pr >> 4, ntile = pr & 15;
            const int m_global = mtile * 256 + (int)rank * 128 + sp * 32 + lane;
            float* orow = outg + (size_t)m_global * 4096 + ntile * 256;
            const float* brow = biasg + ntile * 256;
            uint32_t r[32];
#pragma unroll 1
            for (int cb = 0; cb < 8; ++cb) {
                TCGEN05_LD_X32(r, Dt + cb * 32);
                TCGEN05_WAIT_LD();
#pragma unroll
                for (int c = 0; c < 32; c += 4) {
                    float4 b4 = *(const float4*)(brow + cb * 32 + c);
                    float4 v;
                    v.x = __uint_as_float(r[c + 0]) + b4.x;
                    v.y = __uint_as_float(r[c + 1]) + b4.y;
                    v.z = __uint_as_float(r[c + 2]) + b4.z;
                    v.w = __uint_as_float(r[c + 3]) + b4.w;
                    *(float4*)(orow + cb * 32 + c) = v;
                }
            }
            TCGEN05_FENCE_BEFORE();
            asm volatile("bar.sync 2, 128;" ::: "memory");
            if (tid == 256)
                MBAR_ARRIVE_CLU(sb + OFF_EPI + b * 8, 0);
        }
    }
    // warp 7, follower warp 0: fall through

    __syncthreads();
    if (wid == 0) {
        TCGEN05_RELINQ_CG2();
        TCGEN05_DEALLOC_CG2(tmem, 512);
    }
    asm volatile("barrier.cluster.arrive.aligned;" ::: "memory");
    asm volatile("barrier.cluster.wait.aligned;" ::: "memory");
#else
    // -------- fallback: correct SIMT GEMM (insurance for non-'a' JIT) --------
    const int nthreads = gridDim.x * blockDim.x;
    for (int o = blockIdx.x * blockDim.x + threadIdx.x; o < 16777216; o += nthreads) {
        const int m = o >> 12, n = o & 4095;
        const float* xr = xg + (size_t)m * 4096;
        const __half* bh = g_Bhi + (size_t)n * 4096;
        float acc = 0.0f;
        for (int k = 0; k < 4096; ++k)
            acc += xr[k] * __half2float(bh[k]);
        outg[o] = acc + biasg[n];
    }
#endif
}

// ============================================================================
extern "C" void kernel_launch(void* const* d_in, const int* in_sizes, int n_in,
                              void* d_out, int out_size)
{
    const float* x    = (const float*)d_in[0];
    const float* c0   = (const float*)d_in[1];
    const float* c1   = (const float*)d_in[2];
    const float* c2   = (const float*)d_in[3];
    const float* bias = (const float*)d_in[4];
    float* out = (float*)d_out;

    k_split_x<<<2048, 256>>>(x);
    k_densify<<<256, 256>>>(c0, c1, c2);

    cudaFuncSetAttribute(k_gemm, cudaFuncAttributeMaxDynamicSharedMemorySize,
                         GEMM_SMEM);
    k_gemm<<<152, 384, GEMM_SMEM>>>(x, bias, out);
}

// round 16
// speedup vs baseline: 2.0072x; 2.0072x over previous
#include <cuda_runtime.h>
#include <cuda_fp16.h>
#include <cstdint>

// ============================================================================
// TT-linear = densify W -> 2-term split-fp16 tcgen05 GEMM (cg2, 256x256).
// R16: staging kernels write A_hi/A_lo/B_hi in TILE-MAJOR PRE-SWIZZLED layout
// ([chunk][kstep] 16KB SW128 blocks); the GEMM loader is ONE thread per CTA
// issuing 3 cp.async.bulk (16KB) per kstep with mbarrier complete_tx.
//   y ~= (A_hi + A_lo) . B_hi  (fp16 ins, fp32 accum), rel_err ~2e-4.
// ============================================================================

#if defined(__CUDA_ARCH_FEAT_SM103_ALL) || defined(__CUDA_ARCH_FEAT_SM100_ALL) || defined(__CUDA_ARCH_FEAT_SM101_ALL)
#define HAS_TCGEN05 1
#endif

typedef unsigned long long u64;

// tiled scratch: [32 chunks][64 ksteps] x 16384B swizzled blocks (32MB each)
__device__ __half g_Ahi[4096u * 4096u];
__device__ __half g_Alo[4096u * 4096u];
__device__ __half g_Bhi[4096u * 4096u];

// -------- arch-neutral helpers --------
__device__ __forceinline__ uint32_t smem_u32(const void* p) {
    uint32_t a;
    asm("{ .reg .u64 t; cvta.to.shared.u64 t, %1; cvt.u32.u64 %0, t; }"
        : "=r"(a) : "l"(p));
    return a;
}
__device__ __forceinline__ uint32_t cta_rank() {
    uint32_t r; asm("mov.u32 %0, %%cluster_ctarank;" : "=r"(r)); return r;
}
__device__ __forceinline__ void cpbulk(uint32_t dst, const void* src,
                                       uint32_t bytes, uint32_t mbar) {
    asm volatile(
        "cp.async.bulk.shared::cluster.global.mbarrier::complete_tx::bytes "
        "[%0], [%1], %2, [%3];"
        :: "r"(dst), "l"(src), "r"(bytes), "r"(mbar) : "memory");
}

#define MBARRIER_INIT(addr, cnt) \
    asm volatile("mbarrier.init.shared.b64 [%0], %1;" \
                 :: "r"((uint32_t)(addr)), "r"((uint32_t)(cnt)) : "memory")

#define MBAR_EXPECT_TX(addr, tx) \
    asm volatile("mbarrier.arrive.expect_tx.shared.b64 _, [%0], %1;" \
                 :: "r"((uint32_t)(addr)), "r"((uint32_t)(tx)) : "memory")

#define MBAR_ARRIVE_CLU(addr, rk) \
    asm volatile("{\n\t.reg .b32 ra;\n\t" \
                 "mapa.shared::cluster.u32 ra, %0, %1;\n\t" \
                 "mbarrier.arrive.shared::cluster.b64 _, [ra];\n\t}" \
                 :: "r"((uint32_t)(addr)), "r"((uint32_t)(rk)) : "memory")

#define MBAR_WAIT_ACQ_CTA(addr, par) do {                                   \
    uint32_t _m = (uint32_t)(addr);                                         \
    uint32_t _p = (uint32_t)(par);                                          \
    asm volatile(                                                           \
        "{\n\t.reg .pred P;\n\t"                                            \
        "WL_%=:\n\t"                                                        \
        "mbarrier.try_wait.parity.acquire.cta.shared::cta.b64 P, [%0], %1, 0x989680;\n\t" \
        "@P bra.uni WD_%=;\n\t"                                             \
        "bra.uni WL_%=;\n\t"                                                \
        "WD_%=:\n\t}"                                                       \
        :: "r"(_m), "r"(_p) : "memory");                                    \
} while (0)

#define MBAR_WAIT_RLX_CTA(addr, par) do {                                   \
    uint32_t _m = (uint32_t)(addr);                                         \
    uint32_t _p = (uint32_t)(par);                                          \
    asm volatile(                                                           \
        "{\n\t.reg .pred P;\n\t"                                            \
        "WL_%=:\n\t"                                                        \
        "mbarrier.try_wait.parity.relaxed.cta.shared::cta.b64 P, [%0], %1, 0x989680;\n\t" \
        "@P bra.uni WD_%=;\n\t"                                             \
        "bra.uni WL_%=;\n\t"                                                \
        "WD_%=:\n\t}"                                                       \
        :: "r"(_m), "r"(_p) : "memory");                                    \
} while (0)

#define FENCE_PROXY_ASYNC() asm volatile("fence.proxy.async;" ::: "memory")

#ifdef HAS_TCGEN05
#define TCGEN05_ALLOC_CG2(sa, n) \
    asm volatile("tcgen05.alloc.cta_group::2.sync.aligned.shared::cta.b32 [%0], %1;" \
                 :: "r"((uint32_t)(sa)), "r"((uint32_t)(n)) : "memory")
#define TCGEN05_DEALLOC_CG2(tm, n) \
    asm volatile("tcgen05.dealloc.cta_group::2.sync.aligned.b32 %0, %1;" \
                 :: "r"(tm), "r"((uint32_t)(n)))
#define TCGEN05_RELINQ_CG2() \
    asm volatile("tcgen05.relinquish_alloc_permit.cta_group::2.sync.aligned;")
#define TCGEN05_COMMIT_MC_CG2(mbar, mask) \
    asm volatile("tcgen05.commit.cta_group::2.mbarrier::arrive::one.shared::cluster.multicast::cluster.b64 [%0], %1;" \
                 :: "r"((uint32_t)(mbar)), "h"((uint16_t)(mask)) : "memory")
#define TCGEN05_FENCE_AFTER() \
    asm volatile("tcgen05.fence::after_thread_sync;" ::: "memory")
#define TCGEN05_FENCE_BEFORE() \
    asm volatile("tcgen05.fence::before_thread_sync;" ::: "memory")
#define TCGEN05_WAIT_LD() \
    asm volatile("tcgen05.wait::ld.sync.aligned;" ::: "memory")

#define TCGEN05_LD_X32(r, ta) \
    asm volatile( \
        "tcgen05.ld.sync.aligned.32x32b.x32.b32 " \
        "{%0, %1, %2, %3, %4, %5, %6, %7, " \
        " %8, %9, %10, %11, %12, %13, %14, %15, " \
        " %16, %17, %18, %19, %20, %21, %22, %23, " \
        " %24, %25, %26, %27, %28, %29, %30, %31}, [%32];" \
        : "=r"((r)[0]),  "=r"((r)[1]),  "=r"((r)[2]),  "=r"((r)[3]), \
          "=r"((r)[4]),  "=r"((r)[5]),  "=r"((r)[6]),  "=r"((r)[7]), \
          "=r"((r)[8]),  "=r"((r)[9]),  "=r"((r)[10]), "=r"((r)[11]), \
          "=r"((r)[12]), "=r"((r)[13]), "=r"((r)[14]), "=r"((r)[15]), \
          "=r"((r)[16]), "=r"((r)[17]), "=r"((r)[18]), "=r"((r)[19]), \
          "=r"((r)[20]), "=r"((r)[21]), "=r"((r)[22]), "=r"((r)[23]), \
          "=r"((r)[24]), "=r"((r)[25]), "=r"((r)[26]), "=r"((r)[27]), \
          "=r"((r)[28]), "=r"((r)[29]), "=r"((r)[30]), "=r"((r)[31]) \
        : "r"(ta))

__device__ __forceinline__ void mma_f16_ss_cg2(
    uint32_t d_tmem, u64 a_desc, u64 b_desc, uint32_t idesc, bool en)
{
    uint32_t e = en ? 1u : 0u;
    asm volatile(
        "{\n\t.reg .pred p;\n\t"
        "setp.ne.u32 p, %6, 0;\n\t"
        "tcgen05.mma.cta_group::2.kind::f16 [%0], %1, %2, %3, "
        "{%4, %4, %4, %4, %4, %4, %4, %4}, p;\n\t}"
        :: "r"(d_tmem), "l"(a_desc), "l"(b_desc), "r"(idesc),
           "r"(0u), "r"(0u), "r"(e)
        : "memory");
}

static constexpr u64 SMEM_DESC_SW128 =
    (u64(2) << 61) | (u64(1) << 46) | (u64(64) << 32) | (u64(1) << 16);
__device__ __forceinline__ u64 mk_desc(uint32_t a) {
    return SMEM_DESC_SW128 | ((u64)(a >> 4) & 0x3FFF);
}
#endif  // HAS_TCGEN05

// tiled-block byte offset for element (row in [0,128), chunk16 w8, chunk idx)
__device__ __forceinline__ uint32_t blk_off(uint32_t block, uint32_t row,
                                            uint32_t w8) {
    return block * 16384u + row * 128u + ((w8 << 4) ^ ((row & 7u) << 4));
}

// ============================================================================
// Kernel 1: split x into fp16 hi/lo, tiled+swizzled layout.
// One thread = one 16B chunk (8 k-values).
// ============================================================================
__global__ __launch_bounds__(256) void k_split_x(const float* __restrict__ xg)
{
    const int stride = gridDim.x * blockDim.x;
    for (int q = blockIdx.x * blockDim.x + threadIdx.x; q < 2097152; q += stride) {
        const int m = q >> 9;         // row 0..4095
        const int c = q & 511;        // chunk within row
        const int ks = c >> 3;        // kstep 0..63
        const int w8 = c & 7;         // 16B chunk within 128B kstep-row
        const float4* s = (const float4*)(xg + (size_t)m * 4096 + ks * 64 + w8 * 8);
        float4 v0 = s[0], v1 = s[1];
        __half h[8], l[8];
        float vv[8] = {v0.x, v0.y, v0.z, v0.w, v1.x, v1.y, v1.z, v1.w};
#pragma unroll
        for (int i = 0; i < 8; ++i) {
            h[i] = __float2half_rn(vv[i]);
            l[i] = __float2half_rn(vv[i] - __half2float(h[i]));
        }
        const uint32_t off = blk_off((uint32_t)(m >> 7) * 64u + ks, m & 127, w8);
        *(uint4*)((char*)g_Ahi + off) = *(uint4*)h;
        *(uint4*)((char*)g_Alo + off) = *(uint4*)l;
    }
}

// ============================================================================
// Kernel 2: densify W^T into fp16, tiled+swizzled layout (K-major [n][m]).
// ============================================================================
__global__ __launch_bounds__(256) void k_densify(const float* __restrict__ c0g,
                                                 const float* __restrict__ c1g,
                                                 const float* __restrict__ c2g)
{
    __shared__ float sE[2048];
    __shared__ float sc2[2048];
    const int tid = threadIdx.x;
    const int m1 = blockIdx.x >> 4;
    const int m2 = blockIdx.x & 15;
    const int n1 = tid >> 4, n2 = tid & 15;

    float c0r[8];
#pragma unroll
    for (int r1 = 0; r1 < 8; ++r1) c0r[r1] = c0g[m1 * 128 + n1 * 8 + r1];
#pragma unroll
    for (int r2 = 0; r2 < 8; ++r2) {
        float acc = 0.0f;
#pragma unroll
        for (int r1 = 0; r1 < 8; ++r1)
            acc += c0r[r1] * c1g[(r1 * 16 + m2) * 128 + n2 * 8 + r2];
        sE[tid * 8 + r2] = acc;
    }
    for (int i = tid; i < 2048; i += 256) sc2[i] = c2g[i];
    __syncthreads();

    float Er[8];
#pragma unroll
    for (int r2 = 0; r2 < 8; ++r2) Er[r2] = sE[tid * 8 + r2];

    const int mbase = m1 * 256 + m2 * 16;       // m index of hv[0]
    const int ks = mbase >> 6;
    const int w8a = (mbase & 63) >> 3;

#pragma unroll 1
    for (int n3 = 0; n3 < 16; ++n3) {
        __half hv[16];
#pragma unroll
        for (int m3 = 0; m3 < 16; ++m3) {
            float w = 0.0f;
#pragma unroll
            for (int r2 = 0; r2 < 8; ++r2)
                w += Er[r2] * sc2[r2 * 256 + m3 * 16 + n3];
            hv[m3] = __float2half_rn(w);
        }
        const int n = n1 * 256 + n2 * 16 + n3;
        const uint32_t block = (uint32_t)(n >> 7) * 64u + ks;
        const uint32_t o0 = blk_off(block, n & 127, w8a);
        const uint32_t o1 = blk_off(block, n & 127, w8a + 1);
        *(uint4*)((char*)g_Bhi + o0) = ((uint4*)hv)[0];
        *(uint4*)((char*)g_Bhi + o1) = ((uint4*)hv)[1];
    }
}

// ============================================================================
// Kernel 3: persistent cg2 tcgen05 GEMM, bulk-loaded stages.
// 76 clusters x (3..4) 256x256 tiles. KB=64, 4 stages (48KB each).
// warp0 lane0 (leader): MMA | warp1 lane0: loader | warps 8-11: epilogue.
// ============================================================================
static constexpr int KPT = 64;
static constexpr uint32_t GIDESC =
    (1u << 4) | (32u << 17) | (16u << 24);     // F32 accum, F16 a/b, N=256, M=256

static constexpr int OFF_TMEM  = 0;
static constexpr int OFF_READY = 16;           // 4 x 8B (leader: count 2)
static constexpr int OFF_LRDY  = 48;           // 4 x 8B (follower local, count 1)
static constexpr int OFF_DONE  = 80;           // 4 x 8B
static constexpr int OFF_TDONE = 112;          // 8B
static constexpr int OFF_EPI   = 128;          // 2 x 8B
static constexpr int OFF_TILES = 1024;
static constexpr int STAGE_BYTES = 3 * 16384;  // Ahi, Alo, B (16KB each)
static constexpr int GEMM_SMEM = 1024 + 4 * STAGE_BYTES;   // 197632 B

__global__ __launch_bounds__(384, 1) __cluster_dims__(2, 1, 1)
void k_gemm(const float* __restrict__ xg, const float* __restrict__ biasg,
            float* __restrict__ outg)
{
#ifdef HAS_TCGEN05
    extern __shared__ char smem[];
    const uint32_t sb = smem_u32(smem);
    const int tid = threadIdx.x;
    const int wid = tid >> 5;
    const int lane = tid & 31;
    const uint32_t rank = cta_rank();
    const int cid = blockIdx.x >> 1;               // 0..75

    const int nt = (cid < 28) ? 4 : 3;             // 256 = 3*76 + 28
    const int GT = nt * KPT;

    if (tid == 0) {
#pragma unroll
        for (int s = 0; s < 4; ++s) {
            MBARRIER_INIT(sb + OFF_READY + s * 8, (rank == 0) ? 2 : 1);
            MBARRIER_INIT(sb + OFF_LRDY + s * 8, 1);
            MBARRIER_INIT(sb + OFF_DONE + s * 8, 1);
        }
        MBARRIER_INIT(sb + OFF_TDONE, 1);
        MBARRIER_INIT(sb + OFF_EPI, 2);
        MBARRIER_INIT(sb + OFF_EPI + 8, 2);
    }
    if (wid == 0) TCGEN05_ALLOC_CG2(sb + OFF_TMEM, 512);
    __syncthreads();
    uint32_t tmem;
    asm volatile("ld.shared.b32 %0, [%1];" : "=r"(tmem) : "r"(sb + OFF_TMEM));

    asm volatile("barrier.cluster.arrive.aligned;" ::: "memory");
    asm volatile("barrier.cluster.wait.aligned;" ::: "memory");

    // ---------------- loader: warp 1 lane 0 (both CTAs) ----------------
    if (tid == 32) {
        // completion barrier for this CTA's bulks: leader -> READY, follower -> LRDY
        const uint32_t cbar = sb + ((rank == 0) ? OFF_READY : OFF_LRDY);
        auto issue = [&](int gks) {
            const int t = gks >> 6, k = gks & 63;
            const int pr = cid + t * 76;
            const uint32_t ach = (uint32_t)((pr >> 4) * 2 + (int)rank);
            const uint32_t bch = (uint32_t)((pr & 15) * 2 + (int)rank);
            const uint32_t stg = sb + OFF_TILES + (gks & 3) * STAGE_BYTES;
            const uint32_t bar = cbar + (gks & 3) * 8;
            MBAR_EXPECT_TX(bar, 49152);
            cpbulk(stg,         (const char*)g_Ahi + ((size_t)ach * 64 + k) * 16384, 16384, bar);
            cpbulk(stg + 16384, (const char*)g_Alo + ((size_t)ach * 64 + k) * 16384, 16384, bar);
            cpbulk(stg + 32768, (const char*)g_Bhi + ((size_t)bch * 64 + k) * 16384, 16384, bar);
        };
        issue(0); issue(1); issue(2); issue(3);

        for (int gks = 0; gks < GT; ++gks) {
            const int s = gks & 3;
            const uint32_t par = (uint32_t)((gks >> 2) & 1);
            if (rank == 1) {
                // own data for kstep gks landed -> forward to leader's ready[s]
                MBAR_WAIT_ACQ_CTA(sb + OFF_LRDY + s * 8, par);
                FENCE_PROXY_ASYNC();
                MBAR_ARRIVE_CLU(sb + OFF_READY + s * 8, 0);
            }
            if (gks + 4 < GT) {
                // stage s reusable once MMA(gks) committed done
                MBAR_WAIT_RLX_CTA(sb + OFF_DONE + s * 8, par);
                issue(gks + 4);
            }
        }
    }
    // ---------------- MMA: warp 0 lane 0, leader CTA ----------------
    else if (wid == 0 && rank == 0) {
        if (lane == 0) {
            for (int t = 0; t < nt; ++t) {
                const int b = t & 1;
                const uint32_t Dt = tmem + b * 256;
                if (t >= 2)
                    MBAR_WAIT_RLX_CTA(sb + OFF_EPI + b * 8,
                                      (uint32_t)(((t >> 1) - 1) & 1));
                for (int k = 0; k < KPT; ++k) {
                    const int gks = t * KPT + k;
                    const int s = gks & 3;
                    MBAR_WAIT_ACQ_CTA(sb + OFF_READY + s * 8,
                                      (uint32_t)((gks >> 2) & 1));
                    const uint32_t stg = sb + OFF_TILES + s * STAGE_BYTES;
                    const u64 dA = mk_desc(stg);
                    const u64 dL = mk_desc(stg + 16384);
                    const u64 dB = mk_desc(stg + 32768);
#pragma unroll
                    for (int j = 0; j < 4; ++j)
                        mma_f16_ss_cg2(Dt, dA + j * 2, dB + j * 2, GIDESC,
                                       !(k == 0 && j == 0));
#pragma unroll
                    for (int j = 0; j < 4; ++j)
                        mma_f16_ss_cg2(Dt, dL + j * 2, dB + j * 2, GIDESC, true);
                    TCGEN05_COMMIT_MC_CG2(sb + OFF_DONE + s * 8, 0x3);
                    if (k == KPT - 1)
                        TCGEN05_COMMIT_MC_CG2(sb + OFF_TDONE, 0x3);
                }
            }
        }
    }
    // ---------------- epilogue: warps 8-11 (both CTAs) ----------------
    else if (wid >= 8) {
        const int sp = wid - 8;
        for (int t = 0; t < nt; ++t) {
            MBAR_WAIT_ACQ_CTA(sb + OFF_TDONE, (uint32_t)(t & 1));
            TCGEN05_FENCE_AFTER();
            const int b = t & 1;
            const uint32_t Dt = tmem + b * 256;
            const int pr = cid + t * 76;
            const int mtile = pr >> 4, ntile = pr & 15;
            const int m_global = mtile * 256 + (int)rank * 128 + sp * 32 + lane;
            float* orow = outg + (size_t)m_global * 4096 + ntile * 256;
            const float* brow = biasg + ntile * 256;
            uint32_t r[32];
#pragma unroll 1
            for (int cb = 0; cb < 8; ++cb) {
                TCGEN05_LD_X32(r, Dt + cb * 32);
                TCGEN05_WAIT_LD();
#pragma unroll
                for (int c = 0; c < 32; c += 4) {
                    float4 b4 = *(const float4*)(brow + cb * 32 + c);
                    float4 v;
                    v.x = __uint_as_float(r[c + 0]) + b4.x;
                    v.y = __uint_as_float(r[c + 1]) + b4.y;
                    v.z = __uint_as_float(r[c + 2]) + b4.z;
                    v.w = __uint_as_float(r[c + 3]) + b4.w;
                    *(float4*)(orow + cb * 32 + c) = v;
                }
            }
            TCGEN05_FENCE_BEFORE();
            asm volatile("bar.sync 2, 128;" ::: "memory");
            if (tid == 256)
                MBAR_ARRIVE_CLU(sb + OFF_EPI + b * 8, 0);
        }
    }
    // other warps fall through

    __syncthreads();
    if (wid == 0) {
        TCGEN05_RELINQ_CG2();
        TCGEN05_DEALLOC_CG2(tmem, 512);
    }
    asm volatile("barrier.cluster.arrive.aligned;" ::: "memory");
    asm volatile("barrier.cluster.wait.aligned;" ::: "memory");
#else
    // -------- fallback: correct SIMT GEMM over the tiled B layout ------------
    const int nthreads = gridDim.x * blockDim.x;
    for (int o = blockIdx.x * blockDim.x + threadIdx.x; o < 16777216; o += nthreads) {
        const int m = o >> 12, n = o & 4095;
        const float* xr = xg + (size_t)m * 4096;
        float acc = 0.0f;
        for (int k = 0; k < 4096; ++k) {
            const uint32_t off =
                blk_off((uint32_t)(n >> 7) * 64u + (k >> 6), n & 127,
                        (uint32_t)((k & 63) >> 3)) + (uint32_t)(k & 7) * 2;
            acc += xr[k] * __half2float(*(const __half*)((const char*)g_Bhi + off));
        }
        outg[o] = acc + biasg[n];
    }
#endif
}

// ============================================================================
extern "C" void kernel_launch(void* const* d_in, const int* in_sizes, int n_in,
                              void* d_out, int out_size)
{
    const float* x    = (const float*)d_in[0];
    const float* c0   = (const float*)d_in[1];
    const float* c1   = (const float*)d_in[2];
    const float* c2   = (const float*)d_in[3];
    const float* bias = (const float*)d_in[4];
    float* out = (float*)d_out;

    k_split_x<<<2048, 256>>>(x);
    k_densify<<<256, 256>>>(c0, c1, c2);

    cudaFuncSetAttribute(k_gemm, cudaFuncAttributeMaxDynamicSharedMemorySize,
                         GEMM_SMEM);
    k_gemm<<<152, 384, GEMM_SMEM>>>(x, bias, out);
}

// round 17
// speedup vs baseline: 2.5223x; 1.2566x over previous
#include <cuda_runtime.h>
#include <cuda_fp16.h>
#include <cstdint>

// ============================================================================
// TT-linear = densify W -> single fp16 tcgen05 GEMM (cg2, 256x256 tiles).
// R17: drop BOTH lo terms. y ~= fp16(x) . fp16(W^T) + bias, fp32 accumulate.
//   rel_err ~ sqrt(2) * 2.08e-4 ~ 2.9e-4 (threshold 1e-3).
// Loads per kstep cut 48->32KB (bytes-bound per R16), MMA floor halved,
// 6-stage bulk pipeline in the same 192KB smem.
// ============================================================================

#if defined(__CUDA_ARCH_FEAT_SM103_ALL) || defined(__CUDA_ARCH_FEAT_SM100_ALL) || defined(__CUDA_ARCH_FEAT_SM101_ALL)
#define HAS_TCGEN05 1
#endif

typedef unsigned long long u64;

// tiled scratch: [32 chunks][64 ksteps] x 16384B swizzled blocks (32MB each)
__device__ __half g_Ahi[4096u * 4096u];
__device__ __half g_Bhi[4096u * 4096u];

// -------- arch-neutral helpers --------
__device__ __forceinline__ uint32_t smem_u32(const void* p) {
    uint32_t a;
    asm("{ .reg .u64 t; cvta.to.shared.u64 t, %1; cvt.u32.u64 %0, t; }"
        : "=r"(a) : "l"(p));
    return a;
}
__device__ __forceinline__ uint32_t cta_rank() {
    uint32_t r; asm("mov.u32 %0, %%cluster_ctarank;" : "=r"(r)); return r;
}
__device__ __forceinline__ void cpbulk(uint32_t dst, const void* src,
                                       uint32_t bytes, uint32_t mbar) {
    asm volatile(
        "cp.async.bulk.shared::cluster.global.mbarrier::complete_tx::bytes "
        "[%0], [%1], %2, [%3];"
        :: "r"(dst), "l"(src), "r"(bytes), "r"(mbar) : "memory");
}

#define MBARRIER_INIT(addr, cnt) \
    asm volatile("mbarrier.init.shared.b64 [%0], %1;" \
                 :: "r"((uint32_t)(addr)), "r"((uint32_t)(cnt)) : "memory")

#define MBAR_EXPECT_TX(addr, tx) \
    asm volatile("mbarrier.arrive.expect_tx.shared.b64 _, [%0], %1;" \
                 :: "r"((uint32_t)(addr)), "r"((uint32_t)(tx)) : "memory")

#define MBAR_ARRIVE_CLU(addr, rk) \
    asm volatile("{\n\t.reg .b32 ra;\n\t" \
                 "mapa.shared::cluster.u32 ra, %0, %1;\n\t" \
                 "mbarrier.arrive.shared::cluster.b64 _, [ra];\n\t}" \
                 :: "r"((uint32_t)(addr)), "r"((uint32_t)(rk)) : "memory")

#define MBAR_WAIT_ACQ_CTA(addr, par) do {                                   \
    uint32_t _m = (uint32_t)(addr);                                         \
    uint32_t _p = (uint32_t)(par);                                          \
    asm volatile(                                                           \
        "{\n\t.reg .pred P;\n\t"                                            \
        "WL_%=:\n\t"                                                        \
        "mbarrier.try_wait.parity.acquire.cta.shared::cta.b64 P, [%0], %1, 0x989680;\n\t" \
        "@P bra.uni WD_%=;\n\t"                                             \
        "bra.uni WL_%=;\n\t"                                                \
        "WD_%=:\n\t}"                                                       \
        :: "r"(_m), "r"(_p) : "memory");                                    \
} while (0)

#define MBAR_WAIT_RLX_CTA(addr, par) do {                                   \
    uint32_t _m = (uint32_t)(addr);                                         \
    uint32_t _p = (uint32_t)(par);                                          \
    asm volatile(                                                           \
        "{\n\t.reg .pred P;\n\t"                                            \
        "WL_%=:\n\t"                                                        \
        "mbarrier.try_wait.parity.relaxed.cta.shared::cta.b64 P, [%0], %1, 0x989680;\n\t" \
        "@P bra.uni WD_%=;\n\t"                                             \
        "bra.uni WL_%=;\n\t"                                                \
        "WD_%=:\n\t}"                                                       \
        :: "r"(_m), "r"(_p) : "memory");                                    \
} while (0)

#define FENCE_PROXY_ASYNC() asm volatile("fence.proxy.async;" ::: "memory")

#ifdef HAS_TCGEN05
#define TCGEN05_ALLOC_CG2(sa, n) \
    asm volatile("tcgen05.alloc.cta_group::2.sync.aligned.shared::cta.b32 [%0], %1;" \
                 :: "r"((uint32_t)(sa)), "r"((uint32_t)(n)) : "memory")
#define TCGEN05_DEALLOC_CG2(tm, n) \
    asm volatile("tcgen05.dealloc.cta_group::2.sync.aligned.b32 %0, %1;" \
                 :: "r"(tm), "r"((uint32_t)(n)))
#define TCGEN05_RELINQ_CG2() \
    asm volatile("tcgen05.relinquish_alloc_permit.cta_group::2.sync.aligned;")
#define TCGEN05_COMMIT_MC_CG2(mbar, mask) \
    asm volatile("tcgen05.commit.cta_group::2.mbarrier::arrive::one.shared::cluster.multicast::cluster.b64 [%0], %1;" \
                 :: "r"((uint32_t)(mbar)), "h"((uint16_t)(mask)) : "memory")
#define TCGEN05_FENCE_AFTER() \
    asm volatile("tcgen05.fence::after_thread_sync;" ::: "memory")
#define TCGEN05_FENCE_BEFORE() \
    asm volatile("tcgen05.fence::before_thread_sync;" ::: "memory")
#define TCGEN05_WAIT_LD() \
    asm volatile("tcgen05.wait::ld.sync.aligned;" ::: "memory")

#define TCGEN05_LD_X32(r, ta) \
    asm volatile( \
        "tcgen05.ld.sync.aligned.32x32b.x32.b32 " \
        "{%0, %1, %2, %3, %4, %5, %6, %7, " \
        " %8, %9, %10, %11, %12, %13, %14, %15, " \
        " %16, %17, %18, %19, %20, %21, %22, %23, " \
        " %24, %25, %26, %27, %28, %29, %30, %31}, [%32];" \
        : "=r"((r)[0]),  "=r"((r)[1]),  "=r"((r)[2]),  "=r"((r)[3]), \
          "=r"((r)[4]),  "=r"((r)[5]),  "=r"((r)[6]),  "=r"((r)[7]), \
          "=r"((r)[8]),  "=r"((r)[9]),  "=r"((r)[10]), "=r"((r)[11]), \
          "=r"((r)[12]), "=r"((r)[13]), "=r"((r)[14]), "=r"((r)[15]), \
          "=r"((r)[16]), "=r"((r)[17]), "=r"((r)[18]), "=r"((r)[19]), \
          "=r"((r)[20]), "=r"((r)[21]), "=r"((r)[22]), "=r"((r)[23]), \
          "=r"((r)[24]), "=r"((r)[25]), "=r"((r)[26]), "=r"((r)[27]), \
          "=r"((r)[28]), "=r"((r)[29]), "=r"((r)[30]), "=r"((r)[31]) \
        : "r"(ta))

__device__ __forceinline__ void mma_f16_ss_cg2(
    uint32_t d_tmem, u64 a_desc, u64 b_desc, uint32_t idesc, bool en)
{
    uint32_t e = en ? 1u : 0u;
    asm volatile(
        "{\n\t.reg .pred p;\n\t"
        "setp.ne.u32 p, %6, 0;\n\t"
        "tcgen05.mma.cta_group::2.kind::f16 [%0], %1, %2, %3, "
        "{%4, %4, %4, %4, %4, %4, %4, %4}, p;\n\t}"
        :: "r"(d_tmem), "l"(a_desc), "l"(b_desc), "r"(idesc),
           "r"(0u), "r"(0u), "r"(e)
        : "memory");
}

static constexpr u64 SMEM_DESC_SW128 =
    (u64(2) << 61) | (u64(1) << 46) | (u64(64) << 32) | (u64(1) << 16);
__device__ __forceinline__ u64 mk_desc(uint32_t a) {
    return SMEM_DESC_SW128 | ((u64)(a >> 4) & 0x3FFF);
}
#endif  // HAS_TCGEN05

// tiled-block byte offset (row in [0,128), 16B-chunk w8, block index)
__device__ __forceinline__ uint32_t blk_off(uint32_t block, uint32_t row,
                                            uint32_t w8) {
    return block * 16384u + row * 128u + ((w8 << 4) ^ ((row & 7u) << 4));
}

// ============================================================================
// Kernel 1: x -> fp16 (hi only), tiled+swizzled layout
// ============================================================================
__global__ __launch_bounds__(256) void k_split_x(const float* __restrict__ xg)
{
    const int stride = gridDim.x * blockDim.x;
    for (int q = blockIdx.x * blockDim.x + threadIdx.x; q < 2097152; q += stride) {
        const int m = q >> 9;
        const int c = q & 511;
        const int ks = c >> 3;
        const int w8 = c & 7;
        const float4* s = (const float4*)(xg + (size_t)m * 4096 + ks * 64 + w8 * 8);
        float4 v0 = s[0], v1 = s[1];
        __half h[8];
        h[0] = __float2half_rn(v0.x); h[1] = __float2half_rn(v0.y);
        h[2] = __float2half_rn(v0.z); h[3] = __float2half_rn(v0.w);
        h[4] = __float2half_rn(v1.x); h[5] = __float2half_rn(v1.y);
        h[6] = __float2half_rn(v1.z); h[7] = __float2half_rn(v1.w);
        const uint32_t off = blk_off((uint32_t)(m >> 7) * 64u + ks, m & 127, w8);
        *(uint4*)((char*)g_Ahi + off) = *(uint4*)h;
    }
}

// ============================================================================
// Kernel 2: densify W^T into fp16, tiled+swizzled layout (K-major [n][m])
// ============================================================================
__global__ __launch_bounds__(256) void k_densify(const float* __restrict__ c0g,
                                                 const float* __restrict__ c1g,
                                                 const float* __restrict__ c2g)
{
    __shared__ float sE[2048];
    __shared__ float sc2[2048];
    const int tid = threadIdx.x;
    const int m1 = blockIdx.x >> 4;
    const int m2 = blockIdx.x & 15;
    const int n1 = tid >> 4, n2 = tid & 15;

    float c0r[8];
#pragma unroll
    for (int r1 = 0; r1 < 8; ++r1) c0r[r1] = c0g[m1 * 128 + n1 * 8 + r1];
#pragma unroll
    for (int r2 = 0; r2 < 8; ++r2) {
        float acc = 0.0f;
#pragma unroll
        for (int r1 = 0; r1 < 8; ++r1)
            acc += c0r[r1] * c1g[(r1 * 16 + m2) * 128 + n2 * 8 + r2];
        sE[tid * 8 + r2] = acc;
    }
    for (int i = tid; i < 2048; i += 256) sc2[i] = c2g[i];
    __syncthreads();

    float Er[8];
#pragma unroll
    for (int r2 = 0; r2 < 8; ++r2) Er[r2] = sE[tid * 8 + r2];

    const int mbase = m1 * 256 + m2 * 16;
    const int ks = mbase >> 6;
    const int w8a = (mbase & 63) >> 3;

#pragma unroll 1
    for (int n3 = 0; n3 < 16; ++n3) {
        __half hv[16];
#pragma unroll
        for (int m3 = 0; m3 < 16; ++m3) {
            float w = 0.0f;
#pragma unroll
            for (int r2 = 0; r2 < 8; ++r2)
                w += Er[r2] * sc2[r2 * 256 + m3 * 16 + n3];
            hv[m3] = __float2half_rn(w);
        }
        const int n = n1 * 256 + n2 * 16 + n3;
        const uint32_t block = (uint32_t)(n >> 7) * 64u + ks;
        *(uint4*)((char*)g_Bhi + blk_off(block, n & 127, w8a))     = ((uint4*)hv)[0];
        *(uint4*)((char*)g_Bhi + blk_off(block, n & 127, w8a + 1)) = ((uint4*)hv)[1];
    }
}

// ============================================================================
// Kernel 3: persistent cg2 tcgen05 GEMM, bulk-loaded 6-stage pipeline.
// 76 clusters x (3..4) 256x256 tiles, KB=64.
// warp0 lane0 (leader): MMA | tid 32: loader | warps 8-11: epilogue.
// ============================================================================
static constexpr int KPT = 64;
static constexpr int NSTG = 6;
static constexpr uint32_t GIDESC =
    (1u << 4) | (32u << 17) | (16u << 24);     // F32 accum, F16 a/b, N=256, M=256

static constexpr int OFF_TMEM  = 0;
static constexpr int OFF_READY = 16;           // 6 x 8B (leader count 2)
static constexpr int OFF_LRDY  = 64;           // 6 x 8B (follower local)
static constexpr int OFF_DONE  = 112;          // 6 x 8B
static constexpr int OFF_TDONE = 160;          // 8B
static constexpr int OFF_EPI   = 176;          // 2 x 8B
static constexpr int OFF_TILES = 1024;
static constexpr int STAGE_BYTES = 2 * 16384;  // Ahi, Bhi
static constexpr int GEMM_SMEM = 1024 + NSTG * STAGE_BYTES;   // 197632 B

__global__ __launch_bounds__(384, 1) __cluster_dims__(2, 1, 1)
void k_gemm(const float* __restrict__ xg, const float* __restrict__ biasg,
            float* __restrict__ outg)
{
#ifdef HAS_TCGEN05
    extern __shared__ char smem[];
    const uint32_t sb = smem_u32(smem);
    const int tid = threadIdx.x;
    const int wid = tid >> 5;
    const int lane = tid & 31;
    const uint32_t rank = cta_rank();
    const int cid = blockIdx.x >> 1;               // 0..75

    const int nt = (cid < 28) ? 4 : 3;             // 256 = 3*76 + 28
    const int GT = nt * KPT;

    if (tid == 0) {
#pragma unroll
        for (int s = 0; s < NSTG; ++s) {
            MBARRIER_INIT(sb + OFF_READY + s * 8, (rank == 0) ? 2 : 1);
            MBARRIER_INIT(sb + OFF_LRDY + s * 8, 1);
            MBARRIER_INIT(sb + OFF_DONE + s * 8, 1);
        }
        MBARRIER_INIT(sb + OFF_TDONE, 1);
        MBARRIER_INIT(sb + OFF_EPI, 2);
        MBARRIER_INIT(sb + OFF_EPI + 8, 2);
    }
    if (wid == 0) TCGEN05_ALLOC_CG2(sb + OFF_TMEM, 512);
    __syncthreads();
    uint32_t tmem;
    asm volatile("ld.shared.b32 %0, [%1];" : "=r"(tmem) : "r"(sb + OFF_TMEM));

    asm volatile("barrier.cluster.arrive.aligned;" ::: "memory");
    asm volatile("barrier.cluster.wait.aligned;" ::: "memory");

    // ---------------- loader: warp 1 lane 0 (both CTAs) ----------------
    if (tid == 32) {
        const uint32_t cbar = sb + ((rank == 0) ? OFF_READY : OFF_LRDY);
        auto issue = [&](int gks) {
            const int t = gks / KPT, k = gks % KPT;
            const int pr = cid + t * 76;
            const uint32_t ach = (uint32_t)((pr >> 4) * 2 + (int)rank);
            const uint32_t bch = (uint32_t)((pr & 15) * 2 + (int)rank);
            const int s = gks % NSTG;
            const uint32_t stg = sb + OFF_TILES + s * STAGE_BYTES;
            const uint32_t bar = cbar + s * 8;
            MBAR_EXPECT_TX(bar, 32768);
            cpbulk(stg,         (const char*)g_Ahi + ((size_t)ach * 64 + k) * 16384, 16384, bar);
            cpbulk(stg + 16384, (const char*)g_Bhi + ((size_t)bch * 64 + k) * 16384, 16384, bar);
        };
#pragma unroll
        for (int i = 0; i < NSTG; ++i) issue(i);

        for (int gks = 0; gks < GT; ++gks) {
            const int s = gks % NSTG;
            const uint32_t par = (uint32_t)((gks / NSTG) & 1);
            if (rank == 1) {
                MBAR_WAIT_ACQ_CTA(sb + OFF_LRDY + s * 8, par);
                FENCE_PROXY_ASYNC();
                MBAR_ARRIVE_CLU(sb + OFF_READY + s * 8, 0);
            }
            if (gks + NSTG < GT) {
                MBAR_WAIT_RLX_CTA(sb + OFF_DONE + s * 8, par);
                issue(gks + NSTG);
            }
        }
    }
    // ---------------- MMA: warp 0 lane 0, leader CTA ----------------
    else if (wid == 0 && rank == 0) {
        if (lane == 0) {
            for (int t = 0; t < nt; ++t) {
                const int b = t & 1;
                const uint32_t Dt = tmem + b * 256;
                if (t >= 2)
                    MBAR_WAIT_RLX_CTA(sb + OFF_EPI + b * 8,
                                      (uint32_t)(((t >> 1) - 1) & 1));
                for (int k = 0; k < KPT; ++k) {
                    const int gks = t * KPT + k;
                    const int s = gks % NSTG;
                    MBAR_WAIT_ACQ_CTA(sb + OFF_READY + s * 8,
                                      (uint32_t)((gks / NSTG) & 1));
                    const uint32_t stg = sb + OFF_TILES + s * STAGE_BYTES;
                    const u64 dA = mk_desc(stg);
                    const u64 dB = mk_desc(stg + 16384);
#pragma unroll
                    for (int j = 0; j < 4; ++j)
                        mma_f16_ss_cg2(Dt, dA + j * 2, dB + j * 2, GIDESC,
                                       !(k == 0 && j == 0));
                    TCGEN05_COMMIT_MC_CG2(sb + OFF_DONE + s * 8, 0x3);
                    if (k == KPT - 1)
                        TCGEN05_COMMIT_MC_CG2(sb + OFF_TDONE, 0x3);
                }
            }
        }
    }
    // ---------------- epilogue: warps 8-11 (both CTAs) ----------------
    else if (wid >= 8) {
        const int sp = wid - 8;
        for (int t = 0; t < nt; ++t) {
            MBAR_WAIT_ACQ_CTA(sb + OFF_TDONE, (uint32_t)(t & 1));
            TCGEN05_FENCE_AFTER();
            const int b = t & 1;
            const uint32_t Dt = tmem + b * 256;
            const int pr = cid + t * 76;
            const int mtile = pr >> 4, ntile = pr & 15;
            const int m_global = mtile * 256 + (int)rank * 128 + sp * 32 + lane;
            float* orow = outg + (size_t)m_global * 4096 + ntile * 256;
            const float* brow = biasg + ntile * 256;
            uint32_t r[32];
#pragma unroll 1
            for (int cb = 0; cb < 8; ++cb) {
                TCGEN05_LD_X32(r, Dt + cb * 32);
                TCGEN05_WAIT_LD();
#pragma unroll
                for (int c = 0; c < 32; c += 4) {
                    float4 b4 = *(const float4*)(brow + cb * 32 + c);
                    float4 v;
                    v.x = __uint_as_float(r[c + 0]) + b4.x;
                    v.y = __uint_as_float(r[c + 1]) + b4.y;
                    v.z = __uint_as_float(r[c + 2]) + b4.z;
                    v.w = __uint_as_float(r[c + 3]) + b4.w;
                    *(float4*)(orow + cb * 32 + c) = v;
                }
            }
            TCGEN05_FENCE_BEFORE();
            asm volatile("bar.sync 2, 128;" ::: "memory");
            if (tid == 256)
                MBAR_ARRIVE_CLU(sb + OFF_EPI + b * 8, 0);
        }
    }
    // other warps fall through

    __syncthreads();
    if (wid == 0) {
        TCGEN05_RELINQ_CG2();
        TCGEN05_DEALLOC_CG2(tmem, 512);
    }
    asm volatile("barrier.cluster.arrive.aligned;" ::: "memory");
    asm volatile("barrier.cluster.wait.aligned;" ::: "memory");
#else
    // -------- fallback: correct SIMT GEMM over the tiled B layout ------------
    const int nthreads = gridDim.x * blockDim.x;
    for (int o = blockIdx.x * blockDim.x + threadIdx.x; o < 16777216; o += nthreads) {
        const int m = o >> 12, n = o & 4095;
        const float* xr = xg + (size_t)m * 4096;
        float acc = 0.0f;
        for (int k = 0; k < 4096; ++k) {
            const uint32_t off =
                blk_off((uint32_t)(n >> 7) * 64u + (k >> 6), n & 127,
                        (uint32_t)((k & 63) >> 3)) + (uint32_t)(k & 7) * 2;
            acc += xr[k] * __half2float(*(const __half*)((const char*)g_Bhi + off));
        }
        outg[o] = acc + biasg[n];
    }
#endif
}

// ============================================================================
extern "C" void kernel_launch(void* const* d_in, const int* in_sizes, int n_in,
                              void* d_out, int out_size)
{
    const float* x    = (const float*)d_in[0];
    const float* c0   = (const float*)d_in[1];
    const float* c1   = (const float*)d_in[2];
    const float* c2   = (const float*)d_in[3];
    const float* bias = (const float*)d_in[4];
    float* out = (float*)d_out;

    k_split_x<<<2048, 256>>>(x);
    k_densify<<<256, 256>>>(c0, c1, c2);

    cudaFuncSetAttribute(k_gemm, cudaFuncAttributeMaxDynamicSharedMemorySize,
                         GEMM_SMEM);
    k_gemm<<<152, 384, GEMM_SMEM>>>(x, bias, out);
}